// round 1
// baseline (speedup 1.0000x reference)
#include <cuda_runtime.h>
#include <cuda_bf16.h>

// ---------------------------------------------------------------------------
// Trivariate cubic B-spline evaluation.
//   queries        : [NQ, 3] float32
//   control_points : [64*64*64, 3] float32
//   tx, ty, tz     : [68] float32 open-uniform knot vectors
//   out            : [NQ, 3] float32
//
// Strategy:
//   1) Prologue kernel re-packs control points into a "windowed" layout:
//      for each (ix0, iy, iz), the 4 consecutive x-neighbors of each output
//      component stored as 3 aligned float4s (48B record). This makes the
//      per-query gather exactly 16 pairs x 3 LDG.128 = 48 vector loads.
//   2) Main kernel: one thread per query. Knot span via direct index + exact
//      fix-up against the actual knot array (in shared memory), Cox-de Boor
//      basis (p=3), then 64-point weighted gather-reduce.
// ---------------------------------------------------------------------------

#define NC   64
#define NCEL (NC * NC * NC)

// Windowed control-point scratch: [iz*4096 + iy*64 + ix0] * 3 float4s.
// 64^3 * 3 * 16B = 12.6 MB static device memory (allowed scratch).
__device__ float4 g_win[NCEL * 3];

__global__ void build_windows_kernel(const float* __restrict__ cp) {
    int idx = blockIdx.x * blockDim.x + threadIdx.x;
    if (idx >= NCEL) return;
    int ix0 = idx & 63;
    if (ix0 > 60) return;              // only 61 valid window starts per row
    const float* p = cp + (size_t)idx * 3;
    // 4 consecutive x control points; each is a float3 (stride 3 floats)
    float4 vx = make_float4(p[0], p[3], p[6], p[9]);
    float4 vy = make_float4(p[1], p[4], p[7], p[10]);
    float4 vz = make_float4(p[2], p[5], p[8], p[11]);
    g_win[idx * 3 + 0] = vx;
    g_win[idx * 3 + 1] = vy;
    g_win[idx * 3 + 2] = vz;
}

// Cox-de Boor basis, p=3, using actual knot values from shared memory.
// Returns span k (in [3,63]) and the 4 nonzero basis values N[0..3]
// corresponding to control indices k-3..k.
__device__ __forceinline__ void bspline_basis4(const float* __restrict__ t,
                                               float x, int& kout,
                                               float N0123[4]) {
    float lo = t[3];
    float hi = t[64];
    float xc = fminf(fmaxf(x, lo), hi);

    // Initial guess from uniform interior spacing (t[3+j] = j/61), then
    // exact fix-up against the real knot array -> reproduces searchsorted.
    int k = 3 + (int)floorf(xc * 61.0f);
    k = min(max(k, 3), 63);
    while (k > 3 && xc < t[k]) --k;
    while (k < 63 && xc >= t[k + 1]) ++k;

    float left[4], right[4];
    float N[4];
    N[0] = 1.0f;
#pragma unroll
    for (int r = 1; r <= 3; ++r) {
        left[r]  = xc - t[k + 1 - r];
        right[r] = t[k + r] - xc;
        float saved = 0.0f;
#pragma unroll
        for (int j = 0; j < r; ++j) {
            float temp = N[j] / (right[j + 1] + left[r - j]);
            N[j] = fmaf(right[j + 1], temp, saved);
            saved = left[r - j] * temp;
        }
        N[r] = saved;
    }
    kout = k;
    N0123[0] = N[0];
    N0123[1] = N[1];
    N0123[2] = N[2];
    N0123[3] = N[3];
}

__global__ __launch_bounds__(256)
void spline_eval_kernel(const float* __restrict__ q,
                        const float* __restrict__ tx,
                        const float* __restrict__ ty,
                        const float* __restrict__ tz,
                        float* __restrict__ out, int n) {
    __shared__ float st[3][68];
    int tid = threadIdx.x;
    if (tid < 68) {
        st[0][tid] = tx[tid];
        st[1][tid] = ty[tid];
        st[2][tid] = tz[tid];
    }
    __syncthreads();

    int i = blockIdx.x * blockDim.x + tid;
    if (i >= n) return;

    float qx = q[3 * i + 0];
    float qy = q[3 * i + 1];
    float qz = q[3 * i + 2];

    int kx, ky, kz;
    float bx[4], by[4], bz[4];
    bspline_basis4(st[0], qx, kx, bx);
    bspline_basis4(st[1], qy, ky, by);
    bspline_basis4(st[2], qz, kz, bz);

    int base = (kx - 3) + (ky - 3) * 64 + (kz - 3) * 4096;

    float ax = 0.0f, ay = 0.0f, az = 0.0f;
#pragma unroll
    for (int c = 0; c < 4; ++c) {
#pragma unroll
        for (int b = 0; b < 4; ++b) {
            int w = (base + b * 64 + c * 4096) * 3;
            float wbc = by[b] * bz[c];
            float4 vx = __ldg(&g_win[w + 0]);
            float4 vy = __ldg(&g_win[w + 1]);
            float4 vz = __ldg(&g_win[w + 2]);
            float sx = fmaf(bx[3], vx.w, fmaf(bx[2], vx.z, fmaf(bx[1], vx.y, bx[0] * vx.x)));
            float sy = fmaf(bx[3], vy.w, fmaf(bx[2], vy.z, fmaf(bx[1], vy.y, bx[0] * vy.x)));
            float sz = fmaf(bx[3], vz.w, fmaf(bx[2], vz.z, fmaf(bx[1], vz.y, bx[0] * vz.x)));
            ax = fmaf(wbc, sx, ax);
            ay = fmaf(wbc, sy, ay);
            az = fmaf(wbc, sz, az);
        }
    }

    out[3 * i + 0] = ax;
    out[3 * i + 1] = ay;
    out[3 * i + 2] = az;
}

extern "C" void kernel_launch(void* const* d_in, const int* in_sizes, int n_in,
                              void* d_out, int out_size) {
    const float* queries = (const float*)d_in[0];   // [NQ*3]
    const float* cp      = (const float*)d_in[1];   // [64^3 * 3]
    const float* tx      = (const float*)d_in[2];   // [68]
    const float* ty      = (const float*)d_in[3];
    const float* tz      = (const float*)d_in[4];
    float* out           = (float*)d_out;

    int nq = in_sizes[0] / 3;

    // Prologue: build windowed control-point layout (deterministic each call).
    build_windows_kernel<<<(NCEL + 255) / 256, 256>>>(cp);

    // Main evaluation.
    spline_eval_kernel<<<(nq + 255) / 256, 256>>>(queries, tx, ty, tz, out, nq);
}

// round 2
// speedup vs baseline: 1.8292x; 1.8292x over previous
#include <cuda_runtime.h>
#include <cuda_bf16.h>

// ---------------------------------------------------------------------------
// Trivariate cubic B-spline evaluation, cell-sorted for gather locality.
//
// Pipeline (all graph-capturable, static __device__ scratch only):
//   0) zero histogram
//   1) histogram of queries by cell id (61^3 bins)  [cheap floor key]
//   2) two-level exclusive scan of the histogram
//   3) scatter queries into cell-sorted order as float4{x,y,z,orig_idx}
//   4) build windowed control-point layout (4 x-neighbors per 48B record)
//   5) eval: coalesced sorted-query reads; gathers now share cache lines
//      across lanes; results scattered back to out[orig_idx].
// ---------------------------------------------------------------------------

#define NC     64
#define NCEL   (NC * NC * NC)
#define NQMAX  1000000
#define NBIN   226981              // 61^3
#define CHUNK  1024
#define NCHUNK 222                 // ceil(NBIN/1024)
#define NBINP  (NCHUNK * CHUNK)    // padded bins

__device__ float4 g_win[NCEL * 3];     // 12.6 MB windowed control points
__device__ float4 g_sq[NQMAX];         // 16 MB sorted queries + orig index
__device__ int    g_hist[NBINP];       // per-bin count -> local excl scan/cursor
__device__ int    g_bsum[NCHUNK];      // per-chunk totals
__device__ int    g_choff[NCHUNK];     // per-chunk exclusive offsets

// ---------------------------------------------------------------- utilities

__device__ __forceinline__ int cell_key(float x, float y, float z) {
    int cx = min(60, max(0, (int)(x * 61.0f)));
    int cy = min(60, max(0, (int)(y * 61.0f)));
    int cz = min(60, max(0, (int)(z * 61.0f)));
    return cx + 61 * (cy + 61 * cz);
}

__global__ void zero_hist_kernel() {
    int i = blockIdx.x * blockDim.x + threadIdx.x;
    if (i < NBINP) g_hist[i] = 0;
}

__global__ void hist_kernel(const float* __restrict__ q, int n) {
    int i = blockIdx.x * blockDim.x + threadIdx.x;
    if (i >= n) return;
    int key = cell_key(q[3 * i], q[3 * i + 1], q[3 * i + 2]);
    atomicAdd(&g_hist[key], 1);
}

// Per-chunk exclusive scan (in place); emits chunk totals.
__global__ __launch_bounds__(CHUNK)
void scan_a_kernel() {
    __shared__ int s[CHUNK];
    int t = threadIdx.x;
    int g = blockIdx.x * CHUNK + t;
    int v = g_hist[g];
    s[t] = v;
    __syncthreads();
#pragma unroll
    for (int o = 1; o < CHUNK; o <<= 1) {
        int x = (t >= o) ? s[t - o] : 0;
        __syncthreads();
        s[t] += x;
        __syncthreads();
    }
    g_hist[g] = s[t] - v;                       // exclusive
    if (t == CHUNK - 1) g_bsum[blockIdx.x] = s[t];
}

// Scan the 222 chunk totals (single block).
__global__ __launch_bounds__(256)
void scan_b_kernel() {
    __shared__ int s[256];
    int t = threadIdx.x;
    int v = (t < NCHUNK) ? g_bsum[t] : 0;
    s[t] = v;
    __syncthreads();
#pragma unroll
    for (int o = 1; o < 256; o <<= 1) {
        int x = (t >= o) ? s[t - o] : 0;
        __syncthreads();
        s[t] += x;
        __syncthreads();
    }
    if (t < NCHUNK) g_choff[t] = s[t] - v;      // exclusive
}

__global__ void scatter_kernel(const float* __restrict__ q, int n) {
    int i = blockIdx.x * blockDim.x + threadIdx.x;
    if (i >= n) return;
    float x = q[3 * i], y = q[3 * i + 1], z = q[3 * i + 2];
    int key = cell_key(x, y, z);
    int pos = g_choff[key >> 10] + atomicAdd(&g_hist[key], 1);
    g_sq[pos] = make_float4(x, y, z, __int_as_float(i));
}

// ------------------------------------------------- windowed control points

__global__ void build_windows_kernel(const float* __restrict__ cp) {
    int idx = blockIdx.x * blockDim.x + threadIdx.x;
    if (idx >= NCEL) return;
    int ix0 = idx & 63;
    if (ix0 > 60) return;
    const float* p = cp + (size_t)idx * 3;
    g_win[idx * 3 + 0] = make_float4(p[0], p[3], p[6], p[9]);
    g_win[idx * 3 + 1] = make_float4(p[1], p[4], p[7], p[10]);
    g_win[idx * 3 + 2] = make_float4(p[2], p[5], p[8], p[11]);
}

// ----------------------------------------------------------------- basis

__device__ __forceinline__ void bspline_basis4(const float* __restrict__ t,
                                               float x, int& kout,
                                               float N0123[4]) {
    float xc = fminf(fmaxf(x, t[3]), t[64]);
    int k = 3 + (int)floorf(xc * 61.0f);
    k = min(max(k, 3), 63);
    while (k > 3 && xc < t[k]) --k;
    while (k < 63 && xc >= t[k + 1]) ++k;

    float left[4], right[4], N[4];
    N[0] = 1.0f;
#pragma unroll
    for (int r = 1; r <= 3; ++r) {
        left[r]  = xc - t[k + 1 - r];
        right[r] = t[k + r] - xc;
        float saved = 0.0f;
#pragma unroll
        for (int j = 0; j < r; ++j) {
            float temp = N[j] / (right[j + 1] + left[r - j]);
            N[j] = fmaf(right[j + 1], temp, saved);
            saved = left[r - j] * temp;
        }
        N[r] = saved;
    }
    kout = k;
    N0123[0] = N[0]; N0123[1] = N[1]; N0123[2] = N[2]; N0123[3] = N[3];
}

// ------------------------------------------------------------------- eval

__global__ __launch_bounds__(256)
void spline_eval_kernel(const float* __restrict__ tx,
                        const float* __restrict__ ty,
                        const float* __restrict__ tz,
                        float* __restrict__ out, int n) {
    __shared__ float st[3][68];
    int tid = threadIdx.x;
    if (tid < 68) {
        st[0][tid] = tx[tid];
        st[1][tid] = ty[tid];
        st[2][tid] = tz[tid];
    }
    __syncthreads();

    int i = blockIdx.x * blockDim.x + tid;
    if (i >= n) return;

    float4 qv = g_sq[i];                 // coalesced
    int oi = __float_as_int(qv.w);

    int kx, ky, kz;
    float bx[4], by[4], bz[4];
    bspline_basis4(st[0], qv.x, kx, bx);
    bspline_basis4(st[1], qv.y, ky, by);
    bspline_basis4(st[2], qv.z, kz, bz);

    int base = (kx - 3) + (ky - 3) * 64 + (kz - 3) * 4096;

    float ax = 0.0f, ay = 0.0f, az = 0.0f;
#pragma unroll
    for (int c = 0; c < 4; ++c) {
#pragma unroll
        for (int b = 0; b < 4; ++b) {
            int w = (base + b * 64 + c * 4096) * 3;
            float wbc = by[b] * bz[c];
            float4 vx = __ldg(&g_win[w + 0]);
            float4 vy = __ldg(&g_win[w + 1]);
            float4 vz = __ldg(&g_win[w + 2]);
            float sx = fmaf(bx[3], vx.w, fmaf(bx[2], vx.z, fmaf(bx[1], vx.y, bx[0] * vx.x)));
            float sy = fmaf(bx[3], vy.w, fmaf(bx[2], vy.z, fmaf(bx[1], vy.y, bx[0] * vy.x)));
            float sz = fmaf(bx[3], vz.w, fmaf(bx[2], vz.z, fmaf(bx[1], vz.y, bx[0] * vz.x)));
            ax = fmaf(wbc, sx, ax);
            ay = fmaf(wbc, sy, ay);
            az = fmaf(wbc, sz, az);
        }
    }

    out[3 * oi + 0] = ax;
    out[3 * oi + 1] = ay;
    out[3 * oi + 2] = az;
}

// ---------------------------------------------------------------- launcher

extern "C" void kernel_launch(void* const* d_in, const int* in_sizes, int n_in,
                              void* d_out, int out_size) {
    const float* queries = (const float*)d_in[0];
    const float* cp      = (const float*)d_in[1];
    const float* tx      = (const float*)d_in[2];
    const float* ty      = (const float*)d_in[3];
    const float* tz      = (const float*)d_in[4];
    float* out           = (float*)d_out;

    int nq = in_sizes[0] / 3;
    int qb = (nq + 255) / 256;

    zero_hist_kernel<<<(NBINP + 255) / 256, 256>>>();
    hist_kernel<<<qb, 256>>>(queries, nq);
    scan_a_kernel<<<NCHUNK, CHUNK>>>();
    scan_b_kernel<<<1, 256>>>();
    build_windows_kernel<<<(NCEL + 255) / 256, 256>>>(cp);
    scatter_kernel<<<qb, 256>>>(queries, nq);
    spline_eval_kernel<<<qb, 256>>>(tx, ty, tz, out, nq);
}

// round 3
// speedup vs baseline: 1.8392x; 1.0055x over previous
#include <cuda_runtime.h>
#include <cuda_bf16.h>

// ---------------------------------------------------------------------------
// Trivariate cubic B-spline evaluation, cell-sorted, SoA windowed gathers.
//
// Pipeline:
//   0) zero histogram
//   1) histogram of queries by cell id (61^3 bins)
//   2) warp-shuffle two-level exclusive scan
//   3) scatter queries to sorted order (float4 xyz) + inverse permutation
//   4) build SoA windowed control-point planes (float4 per component)
//   5) eval: coalesced query reads, ~1-line gathers, coalesced staged output
//   6) unsort: one scattered LDG.128 per query -> coalesced out
// ---------------------------------------------------------------------------

#define NC     64
#define NCEL   (NC * NC * NC)
#define NQMAX  1000000
#define NBIN   226981              // 61^3
#define CHUNK  1024
#define NCHUNK 222                 // ceil(NBIN/1024)
#define NBINP  (NCHUNK * CHUNK)

__device__ float4 g_winx[NCEL];        // SoA windowed planes (4 x-neighbors)
__device__ float4 g_winy[NCEL];
__device__ float4 g_winz[NCEL];
__device__ float4 g_sq[NQMAX];         // sorted queries (xyz, pad)
__device__ float4 g_sout[NQMAX];       // sorted results (xyz, pad)
__device__ int    g_inv[NQMAX];        // orig index -> sorted position
__device__ int    g_hist[NBINP];
__device__ int    g_bsum[NCHUNK];
__device__ int    g_choff[NCHUNK];

// ---------------------------------------------------------------- utilities

__device__ __forceinline__ int cell_key(float x, float y, float z) {
    int cx = min(60, max(0, (int)(x * 61.0f)));
    int cy = min(60, max(0, (int)(y * 61.0f)));
    int cz = min(60, max(0, (int)(z * 61.0f)));
    return cx + 61 * (cy + 61 * cz);
}

__global__ void zero_hist_kernel() {
    int i = blockIdx.x * blockDim.x + threadIdx.x;
    if (i < NBINP) g_hist[i] = 0;
}

__global__ void hist_kernel(const float* __restrict__ q, int n) {
    int i = blockIdx.x * blockDim.x + threadIdx.x;
    if (i >= n) return;
    int key = cell_key(q[3 * i], q[3 * i + 1], q[3 * i + 2]);
    atomicAdd(&g_hist[key], 1);
}

// Warp-shuffle inclusive scan within a warp.
__device__ __forceinline__ int warp_incl_scan(int v, int lane) {
#pragma unroll
    for (int o = 1; o < 32; o <<= 1) {
        int u = __shfl_up_sync(0xffffffffu, v, o);
        if (lane >= o) v += u;
    }
    return v;
}

// Per-chunk exclusive scan of g_hist (1024 threads, 32 warps, 2 syncs).
__global__ __launch_bounds__(CHUNK)
void scan_a_kernel() {
    __shared__ int swarp[32];
    int t = threadIdx.x;
    int lane = t & 31, w = t >> 5;
    int g = blockIdx.x * CHUNK + t;
    int v = g_hist[g];
    int incl = warp_incl_scan(v, lane);
    if (lane == 31) swarp[w] = incl;
    __syncthreads();
    if (w == 0) {
        int s = swarp[lane];
        int si = warp_incl_scan(s, lane);
        swarp[lane] = si - s;                       // exclusive warp offsets
        if (lane == 31) g_bsum[blockIdx.x] = si;    // chunk total
    }
    __syncthreads();
    g_hist[g] = swarp[w] + incl - v;                // exclusive within chunk
}

// Scan the 222 chunk totals (256 threads, 8 warps).
__global__ __launch_bounds__(256)
void scan_b_kernel() {
    __shared__ int swarp[8];
    int t = threadIdx.x;
    int lane = t & 31, w = t >> 5;
    int v = (t < NCHUNK) ? g_bsum[t] : 0;
    int incl = warp_incl_scan(v, lane);
    if (lane == 31) swarp[w] = incl;
    __syncthreads();
    int off = 0;
#pragma unroll
    for (int j = 0; j < 8; ++j) off += (j < w) ? swarp[j] : 0;
    if (t < NCHUNK) g_choff[t] = off + incl - v;
}

__global__ void scatter_kernel(const float* __restrict__ q, int n) {
    int i = blockIdx.x * blockDim.x + threadIdx.x;
    if (i >= n) return;
    float x = q[3 * i], y = q[3 * i + 1], z = q[3 * i + 2];
    int key = cell_key(x, y, z);
    int pos = g_choff[key >> 10] + atomicAdd(&g_hist[key], 1);
    g_sq[pos] = make_float4(x, y, z, 0.0f);
    g_inv[i] = pos;
}

// ------------------------------------------------- windowed control points

__global__ void build_windows_kernel(const float* __restrict__ cp) {
    int idx = blockIdx.x * blockDim.x + threadIdx.x;
    if (idx >= NCEL) return;
    int ix0 = idx & 63;
    if (ix0 > 60) return;
    const float* p = cp + (size_t)idx * 3;
    g_winx[idx] = make_float4(p[0], p[3], p[6], p[9]);
    g_winy[idx] = make_float4(p[1], p[4], p[7], p[10]);
    g_winz[idx] = make_float4(p[2], p[5], p[8], p[11]);
}

// ----------------------------------------------------------------- basis

__device__ __forceinline__ void bspline_basis4(const float* __restrict__ t,
                                               float x, int& kout,
                                               float N0123[4]) {
    float xc = fminf(fmaxf(x, t[3]), t[64]);
    int k = 3 + (int)floorf(xc * 61.0f);
    k = min(max(k, 3), 63);
    while (k > 3 && xc < t[k]) --k;
    while (k < 63 && xc >= t[k + 1]) ++k;

    float left[4], right[4], N[4];
    N[0] = 1.0f;
#pragma unroll
    for (int r = 1; r <= 3; ++r) {
        left[r]  = xc - t[k + 1 - r];
        right[r] = t[k + r] - xc;
        float saved = 0.0f;
#pragma unroll
        for (int j = 0; j < r; ++j) {
            float temp = N[j] / (right[j + 1] + left[r - j]);
            N[j] = fmaf(right[j + 1], temp, saved);
            saved = left[r - j] * temp;
        }
        N[r] = saved;
    }
    kout = k;
    N0123[0] = N[0]; N0123[1] = N[1]; N0123[2] = N[2]; N0123[3] = N[3];
}

// ------------------------------------------------------------------- eval

__global__ __launch_bounds__(256)
void spline_eval_kernel(const float* __restrict__ tx,
                        const float* __restrict__ ty,
                        const float* __restrict__ tz, int n) {
    __shared__ float st[3][68];
    int tid = threadIdx.x;
    if (tid < 68) {
        st[0][tid] = tx[tid];
        st[1][tid] = ty[tid];
        st[2][tid] = tz[tid];
    }
    __syncthreads();

    int i = blockIdx.x * blockDim.x + tid;
    if (i >= n) return;

    float4 qv = g_sq[i];

    int kx, ky, kz;
    float bx[4], by[4], bz[4];
    bspline_basis4(st[0], qv.x, kx, bx);
    bspline_basis4(st[1], qv.y, ky, by);
    bspline_basis4(st[2], qv.z, kz, bz);

    int base = (kx - 3) + (ky - 3) * 64 + (kz - 3) * 4096;

    float ax = 0.0f, ay = 0.0f, az = 0.0f;
#pragma unroll
    for (int c = 0; c < 4; ++c) {
#pragma unroll
        for (int b = 0; b < 4; ++b) {
            int w = base + b * 64 + c * 4096;
            float wbc = by[b] * bz[c];
            float4 vx = __ldg(&g_winx[w]);
            float4 vy = __ldg(&g_winy[w]);
            float4 vz = __ldg(&g_winz[w]);
            float sx = fmaf(bx[3], vx.w, fmaf(bx[2], vx.z, fmaf(bx[1], vx.y, bx[0] * vx.x)));
            float sy = fmaf(bx[3], vy.w, fmaf(bx[2], vy.z, fmaf(bx[1], vy.y, bx[0] * vy.x)));
            float sz = fmaf(bx[3], vz.w, fmaf(bx[2], vz.z, fmaf(bx[1], vz.y, bx[0] * vz.x)));
            ax = fmaf(wbc, sx, ax);
            ay = fmaf(wbc, sy, ay);
            az = fmaf(wbc, sz, az);
        }
    }

    g_sout[i] = make_float4(ax, ay, az, 0.0f);   // coalesced staged output
}

// Permute staged results back to original order.
__global__ __launch_bounds__(256)
void unsort_kernel(float* __restrict__ out, int n) {
    int i = blockIdx.x * blockDim.x + threadIdx.x;
    if (i >= n) return;
    int p = g_inv[i];                 // coalesced
    float4 r = __ldg(&g_sout[p]);     // one scattered 16B load
    out[3 * i + 0] = r.x;             // coalesced stores
    out[3 * i + 1] = r.y;
    out[3 * i + 2] = r.z;
}

// ---------------------------------------------------------------- launcher

extern "C" void kernel_launch(void* const* d_in, const int* in_sizes, int n_in,
                              void* d_out, int out_size) {
    const float* queries = (const float*)d_in[0];
    const float* cp      = (const float*)d_in[1];
    const float* tx      = (const float*)d_in[2];
    const float* ty      = (const float*)d_in[3];
    const float* tz      = (const float*)d_in[4];
    float* out           = (float*)d_out;

    int nq = in_sizes[0] / 3;
    int qb = (nq + 255) / 256;

    zero_hist_kernel<<<(NBINP + 255) / 256, 256>>>();
    hist_kernel<<<qb, 256>>>(queries, nq);
    scan_a_kernel<<<NCHUNK, CHUNK>>>();
    scan_b_kernel<<<1, 256>>>();
    build_windows_kernel<<<(NCEL + 255) / 256, 256>>>(cp);
    scatter_kernel<<<qb, 256>>>(queries, nq);
    spline_eval_kernel<<<qb, 256>>>(tx, ty, tz, nq);
    unsort_kernel<<<qb, 256>>>(out, nq);
}